// round 1
// baseline (speedup 1.0000x reference)
#include <cuda_runtime.h>
#include <math.h>

// Problem constants
#define T_STEPS 256
#define BATCH   64
#define DIN     512
#define HID     1024
#define DH      (DIN + HID)     // 1536
#define NG      (4 * HID)       // 4096  (4 gates)
#define M1      (T_STEPS * BATCH) // 16384

// -------- device scratch (static allocations only; no cudaMalloc allowed) ----
__device__ float g_WxT[DIN * NG];          // 8 MB   [k][n]
__device__ float g_WhT[HID * NG];          // 16 MB  [k][n]
__device__ float g_ball[NG];               // 16 KB
__device__ float g_Gx[(size_t)M1 * NG];    // 256 MB : x-projection for all t (includes bias)
__device__ float g_h[BATCH * HID];         // current hidden
__device__ float g_c[BATCH * HID];         // current cell
__device__ float g_part[4][BATCH * NG];    // 4 MB: K-split partial sums of recurrent GEMM

// ---------------------------------------------------------------------------
// init: zero h0/c0, build concatenated bias
// ---------------------------------------------------------------------------
__global__ void init_kernel(const float* __restrict__ bf, const float* __restrict__ bi,
                            const float* __restrict__ bg, const float* __restrict__ bo) {
    int idx = blockIdx.x * blockDim.x + threadIdx.x;
    if (idx < BATCH * HID) { g_h[idx] = 0.f; g_c[idx] = 0.f; }
    if (idx < NG) {
        int gate = idx >> 10;
        int j = idx & (HID - 1);
        const float* b = (gate == 0) ? bf : (gate == 1) ? bi : (gate == 2) ? bg : bo;
        g_ball[idx] = b[j];
    }
}

// ---------------------------------------------------------------------------
// pack: transpose W_all [4096, 1536] (rows = gate weights) into K-major
//       g_WxT[k][n] (k<512) and g_WhT[k-512][n] (k>=512)
// ---------------------------------------------------------------------------
__global__ void pack_kernel(const float* __restrict__ Wf, const float* __restrict__ Wi,
                            const float* __restrict__ Wg, const float* __restrict__ Wo) {
    __shared__ float tile[32][33];
    int tx = threadIdx.x, ty = threadIdx.y;
    int k0 = blockIdx.x * 32;   // k in [0,1536)
    int n0 = blockIdx.y * 32;   // n in [0,4096)
    int gate = n0 >> 10;        // 32-tiles never cross the 1024 gate boundary
    const float* W = (gate == 0) ? Wf : (gate == 1) ? Wi : (gate == 2) ? Wg : Wo;
    int j0 = n0 & (HID - 1);

    // coalesced read along k
    tile[ty][tx] = W[(size_t)(j0 + ty) * DH + (k0 + tx)];
    __syncthreads();

    // coalesced write along n
    int k = k0 + ty;
    int n = n0 + tx;
    float v = tile[tx][ty];
    if (k < DIN) g_WxT[(size_t)k * NG + n] = v;
    else         g_WhT[(size_t)(k - DIN) * NG + n] = v;
}

// ---------------------------------------------------------------------------
// gemm_x: Gx[m][n] = sum_k X[m][k] * WxT[k][n] + ball[n]
//         M=16384, N=4096, K=512.  64x64 tile, 256 threads, 4x4 per thread.
// ---------------------------------------------------------------------------
__global__ void __launch_bounds__(256) gemm_x_kernel(const float* __restrict__ X) {
    __shared__ float As[16][64];
    __shared__ float Bs[16][64];

    int tid = threadIdx.x;
    int tx = tid & 15;          // 0..15 -> 4 cols each
    int ty = tid >> 4;          // 0..15 -> 4 rows each
    int n0 = blockIdx.x * 64;
    int m0 = blockIdx.y * 64;

    float acc[4][4];
    #pragma unroll
    for (int r = 0; r < 4; r++)
        #pragma unroll
        for (int c = 0; c < 4; c++) acc[r][c] = 0.f;

    // A-load mapping: 64 rows x 16 k, 4 consecutive k per thread (float4)
    int am = tid >> 2;              // 0..63
    int akg = (tid & 3) * 4;        // 0,4,8,12
    // B-load mapping: 16 k-rows x 64 n, float4 along n
    int bk = tid >> 4;              // 0..15
    int bn = (tid & 15) * 4;        // 0..60

    for (int k0 = 0; k0 < DIN; k0 += 16) {
        float4 av = *(const float4*)(X + (size_t)(m0 + am) * DIN + k0 + akg);
        As[akg + 0][am] = av.x; As[akg + 1][am] = av.y;
        As[akg + 2][am] = av.z; As[akg + 3][am] = av.w;

        float4 bv = *(const float4*)(&g_WxT[(size_t)(k0 + bk) * NG + n0 + bn]);
        *(float4*)&Bs[bk][bn] = bv;
        __syncthreads();

        #pragma unroll
        for (int kk = 0; kk < 16; kk++) {
            float a[4], b[4];
            #pragma unroll
            for (int r = 0; r < 4; r++) a[r] = As[kk][ty * 4 + r];
            #pragma unroll
            for (int c = 0; c < 4; c++) b[c] = Bs[kk][tx * 4 + c];
            #pragma unroll
            for (int r = 0; r < 4; r++)
                #pragma unroll
                for (int c = 0; c < 4; c++) acc[r][c] = fmaf(a[r], b[c], acc[r][c]);
        }
        __syncthreads();
    }

    #pragma unroll
    for (int r = 0; r < 4; r++) {
        int m = m0 + ty * 4 + r;
        #pragma unroll
        for (int c = 0; c < 4; c++) {
            int n = n0 + tx * 4 + c;
            g_Gx[(size_t)m * NG + n] = acc[r][c] + g_ball[n];
        }
    }
}

// ---------------------------------------------------------------------------
// gemm_h (per timestep, K-split x4): part[s][b][n] = sum_{k in split s} h[b][k]*WhT[k][n]
//   grid: (N/64 = 64, 4) ; M = 64 (full batch), per-split K = 256
// ---------------------------------------------------------------------------
__global__ void __launch_bounds__(256) gemm_h_kernel() {
    __shared__ float As[16][64];
    __shared__ float Bs[16][64];

    int tid = threadIdx.x;
    int tx = tid & 15;
    int ty = tid >> 4;
    int n0 = blockIdx.x * 64;
    int ks = blockIdx.y;            // 0..3
    int kbase = ks * 256;

    float acc[4][4];
    #pragma unroll
    for (int r = 0; r < 4; r++)
        #pragma unroll
        for (int c = 0; c < 4; c++) acc[r][c] = 0.f;

    int am = tid >> 2;
    int akg = (tid & 3) * 4;
    int bk = tid >> 4;
    int bn = (tid & 15) * 4;

    for (int k0 = kbase; k0 < kbase + 256; k0 += 16) {
        float4 av = *(const float4*)(&g_h[(size_t)am * HID + k0 + akg]);
        As[akg + 0][am] = av.x; As[akg + 1][am] = av.y;
        As[akg + 2][am] = av.z; As[akg + 3][am] = av.w;

        float4 bv = *(const float4*)(&g_WhT[(size_t)(k0 + bk) * NG + n0 + bn]);
        *(float4*)&Bs[bk][bn] = bv;
        __syncthreads();

        #pragma unroll
        for (int kk = 0; kk < 16; kk++) {
            float a[4], b[4];
            #pragma unroll
            for (int r = 0; r < 4; r++) a[r] = As[kk][ty * 4 + r];
            #pragma unroll
            for (int c = 0; c < 4; c++) b[c] = Bs[kk][tx * 4 + c];
            #pragma unroll
            for (int r = 0; r < 4; r++)
                #pragma unroll
                for (int c = 0; c < 4; c++) acc[r][c] = fmaf(a[r], b[c], acc[r][c]);
        }
        __syncthreads();
    }

    float* dst = g_part[ks];
    #pragma unroll
    for (int r = 0; r < 4; r++) {
        int m = ty * 4 + r;
        #pragma unroll
        for (int c = 0; c < 4; c++) {
            int n = n0 + tx * 4 + c;
            dst[(size_t)m * NG + n] = acc[r][c];
        }
    }
}

// ---------------------------------------------------------------------------
// per-timestep epilogue: gates = Gx[t] + sum(partials); activations; update c,h;
// write outputs[t]
// ---------------------------------------------------------------------------
__device__ __forceinline__ float sigmoidf_(float x) { return 1.0f / (1.0f + expf(-x)); }

__global__ void __launch_bounds__(256) step_epi_kernel(float* __restrict__ out, int t) {
    int idx = blockIdx.x * blockDim.x + threadIdx.x;  // 0..65535
    int b = idx >> 10;
    int j = idx & (HID - 1);

    const float* gx = g_Gx + ((size_t)t * BATCH + b) * NG;
    size_t base = (size_t)b * NG;

    float f = gx[j]           + g_part[0][base + j]            + g_part[1][base + j]
                              + g_part[2][base + j]            + g_part[3][base + j];
    float i = gx[HID + j]     + g_part[0][base + HID + j]      + g_part[1][base + HID + j]
                              + g_part[2][base + HID + j]      + g_part[3][base + HID + j];
    float g = gx[2 * HID + j] + g_part[0][base + 2 * HID + j]  + g_part[1][base + 2 * HID + j]
                              + g_part[2][base + 2 * HID + j]  + g_part[3][base + 2 * HID + j];
    float o = gx[3 * HID + j] + g_part[0][base + 3 * HID + j]  + g_part[1][base + 3 * HID + j]
                              + g_part[2][base + 3 * HID + j]  + g_part[3][base + 3 * HID + j];

    f = sigmoidf_(f);
    i = sigmoidf_(i);
    g = tanhf(g);
    o = sigmoidf_(o);

    float c = f * g_c[idx] + i * g;
    float h = o * tanhf(c);
    g_c[idx] = c;
    g_h[idx] = h;

    out[(size_t)t * (BATCH * HID) + idx] = h;
}

// tail: write hT, cT
__global__ void tail_kernel(float* __restrict__ out_hT, float* __restrict__ out_cT) {
    int idx = blockIdx.x * blockDim.x + threadIdx.x;
    if (idx < BATCH * HID) {
        out_hT[idx] = g_h[idx];
        out_cT[idx] = g_c[idx];
    }
}

// ---------------------------------------------------------------------------
extern "C" void kernel_launch(void* const* d_in, const int* in_sizes, int n_in,
                              void* d_out, int out_size) {
    const float* X  = (const float*)d_in[0];
    const float* Wf = (const float*)d_in[1];
    const float* bf = (const float*)d_in[2];
    const float* Wi = (const float*)d_in[3];
    const float* bi = (const float*)d_in[4];
    const float* Wg = (const float*)d_in[5];
    const float* bg = (const float*)d_in[6];
    const float* Wo = (const float*)d_in[7];
    const float* bo = (const float*)d_in[8];
    float* out = (float*)d_out;

    // prologue: bias/state init + weight repack + input projection for all t
    init_kernel<<<256, 256>>>(bf, bi, bg, bo);
    pack_kernel<<<dim3(DH / 32, NG / 32), dim3(32, 32)>>>(Wf, Wi, Wg, Wo);
    gemm_x_kernel<<<dim3(NG / 64, M1 / 64), 256>>>(X);

    // sequential recurrence
    for (int t = 0; t < T_STEPS; t++) {
        gemm_h_kernel<<<dim3(NG / 64, 4), 256>>>();
        step_epi_kernel<<<(BATCH * HID) / 256, 256>>>(out, t);
    }

    // hT / cT (present in flattened output after outputs[T,B,H])
    const long long OUT_MAIN = (long long)T_STEPS * BATCH * HID;       // 16,777,216
    if ((long long)out_size >= OUT_MAIN + 2LL * BATCH * HID) {
        tail_kernel<<<(BATCH * HID + 255) / 256, 256>>>(out + OUT_MAIN,
                                                        out + OUT_MAIN + BATCH * HID);
    }
}